// round 3
// baseline (speedup 1.0000x reference)
#include <cuda_runtime.h>

#define T    4096
#define DIM  1024
#define HID  4096
#define E    8
#define KTOP 2

#define BM 128
#define BN 128
#define BKK 8
#define MT (T / BM)   // 32 max row-tiles per expert

// ---------------- scratch (static device memory; no allocations) -------------
__device__ int   g_counts[E];
__device__ int   g_fill[E];
__device__ int   g_offsets[E + 1];
__device__ int   g_topk_e[T * KTOP];
__device__ float g_topk_p[T * KTOP];
__device__ int   g_row_token[T * KTOP];
__device__ int   g_tok_row[T * KTOP];
__device__ float g_H[(size_t)T * KTOP * HID];     // 128 MB: relu(x@w1+b1) rows
__device__ float g_Hout[(size_t)T * KTOP * DIM];  // 32 MB: per-row h@w2

// ---------------- init ------------------------------------------------------
__global__ void init_kernel() {
    int i = threadIdx.x;
    if (i < E) { g_counts[i] = 0; g_fill[i] = 0; }
}

// ---------------- gating: one warp per token --------------------------------
__global__ void gating_kernel(const float* __restrict__ x,
                              const float* __restrict__ gw,
                              const float* __restrict__ gb) {
    int warp = (blockIdx.x * blockDim.x + threadIdx.x) >> 5;
    int lane = threadIdx.x & 31;
    if (warp >= T) return;
    const float* xr = x + (size_t)warp * DIM;

    float acc[E];
#pragma unroll
    for (int e = 0; e < E; e++) acc[e] = 0.f;

    for (int d = lane; d < DIM; d += 32) {
        float xv = xr[d];
        float4 g0 = *(const float4*)(gw + d * E);
        float4 g1 = *(const float4*)(gw + d * E + 4);
        acc[0] += xv * g0.x; acc[1] += xv * g0.y;
        acc[2] += xv * g0.z; acc[3] += xv * g0.w;
        acc[4] += xv * g1.x; acc[5] += xv * g1.y;
        acc[6] += xv * g1.z; acc[7] += xv * g1.w;
    }
#pragma unroll
    for (int e = 0; e < E; e++) {
#pragma unroll
        for (int off = 16; off > 0; off >>= 1)
            acc[e] += __shfl_down_sync(0xffffffffu, acc[e], off);
    }

    if (lane == 0) {
        float lg[E];
        float m = -1e30f;
#pragma unroll
        for (int e = 0; e < E; e++) { lg[e] = acc[e] + gb[e]; m = fmaxf(m, lg[e]); }
        float s = 0.f;
#pragma unroll
        for (int e = 0; e < E; e++) { lg[e] = expf(lg[e] - m); s += lg[e]; }
        // top-2 (ties -> lower index, matching jax.lax.top_k)
        int e1 = 0;
#pragma unroll
        for (int e = 1; e < E; e++) if (lg[e] > lg[e1]) e1 = e;
        int e2 = (e1 == 0) ? 1 : 0;
#pragma unroll
        for (int e = 0; e < E; e++) if (e != e1 && e != e2 && lg[e] > lg[e2]) e2 = e;
        float inv = 1.0f / s;
        g_topk_e[warp * 2 + 0] = e1;
        g_topk_e[warp * 2 + 1] = e2;
        g_topk_p[warp * 2 + 0] = lg[e1] * inv;
        g_topk_p[warp * 2 + 1] = lg[e2] * inv;
        atomicAdd(&g_counts[e1], 1);
        atomicAdd(&g_counts[e2], 1);
    }
}

// ---------------- tiny exclusive scan over E --------------------------------
__global__ void scan_kernel() {
    if (threadIdx.x == 0) {
        int acc = 0;
        g_offsets[0] = 0;
        for (int e = 0; e < E; e++) { acc += g_counts[e]; g_offsets[e + 1] = acc; }
    }
}

// ---------------- assign rows (order within expert is irrelevant) -----------
__global__ void assign_kernel() {
    int t = blockIdx.x * blockDim.x + threadIdx.x;
    if (t >= T) return;
#pragma unroll
    for (int k = 0; k < KTOP; k++) {
        int e = g_topk_e[t * 2 + k];
        int slot = atomicAdd(&g_fill[e], 1);
        int row = g_offsets[e] + slot;
        g_row_token[row] = t;
        g_tok_row[t * 2 + k] = row;
    }
}

// ---------------- grouped GEMM1: H = relu(gather(x) @ w1[e] + b1[e]) --------
__global__ void __launch_bounds__(256)
gemm1_kernel(const float* __restrict__ x,
             const float* __restrict__ w1,
             const float* __restrict__ b1) {
    int e  = blockIdx.y >> 5;   // / MT
    int mt = blockIdx.y & 31;
    int cnt = g_counts[e];
    int m0 = mt * BM;
    if (m0 >= cnt) return;
    int n0 = blockIdx.x * BN;
    int base = g_offsets[e];

    __shared__ float As[BKK][BM];
    __shared__ float Bs[BKK][BN];
    __shared__ int   toks[BM];

    int tid = threadIdx.x;
    if (tid < BM) {
        int m = m0 + tid;
        toks[tid] = g_row_token[base + ((m < cnt) ? m : 0)];
    }
    __syncthreads();

    int tx = tid & 15;   // n direction (16)
    int ty = tid >> 4;   // m direction (16)
    float acc[8][8];
#pragma unroll
    for (int i = 0; i < 8; i++)
#pragma unroll
        for (int j = 0; j < 8; j++) acc[i][j] = 0.f;

    const float* wB = w1 + (size_t)e * DIM * HID;

    int arow = tid >> 1;          // 128 rows, 2 threads/row
    int aseg = (tid & 1) * 4;
    int brow = tid >> 5;          // 8 k-rows, 32 threads/row
    int bcol = (tid & 31) * 4;

    for (int k0 = 0; k0 < DIM; k0 += BKK) {
        float4 av = *(const float4*)(x + (size_t)toks[arow] * DIM + k0 + aseg);
        As[aseg + 0][arow] = av.x;
        As[aseg + 1][arow] = av.y;
        As[aseg + 2][arow] = av.z;
        As[aseg + 3][arow] = av.w;
        float4 bv = *(const float4*)(wB + (size_t)(k0 + brow) * HID + n0 + bcol);
        *(float4*)&Bs[brow][bcol] = bv;
        __syncthreads();
#pragma unroll
        for (int k = 0; k < BKK; k++) {
            float4 a0 = *(const float4*)&As[k][ty * 8];
            float4 a1 = *(const float4*)&As[k][ty * 8 + 4];
            float4 b0 = *(const float4*)&Bs[k][tx * 8];
            float4 b1v = *(const float4*)&Bs[k][tx * 8 + 4];
            float ra[8] = {a0.x, a0.y, a0.z, a0.w, a1.x, a1.y, a1.z, a1.w};
            float rb[8] = {b0.x, b0.y, b0.z, b0.w, b1v.x, b1v.y, b1v.z, b1v.w};
#pragma unroll
            for (int i = 0; i < 8; i++)
#pragma unroll
                for (int j = 0; j < 8; j++) acc[i][j] += ra[i] * rb[j];
        }
        __syncthreads();
    }

#pragma unroll
    for (int i = 0; i < 8; i++) {
        int m = m0 + ty * 8 + i;
        if (m >= cnt) continue;
        size_t hbase = (size_t)(base + m) * HID + n0 + tx * 8;
#pragma unroll
        for (int j = 0; j < 8; j++) {
            float v = acc[i][j] + b1[e * HID + n0 + tx * 8 + j];
            g_H[hbase + j] = fmaxf(v, 0.f);
        }
    }
}

// ---------------- grouped GEMM2: Hout = H @ w2[e] ---------------------------
__global__ void __launch_bounds__(256)
gemm2_kernel(const float* __restrict__ w2) {
    int e  = blockIdx.y >> 5;
    int mt = blockIdx.y & 31;
    int cnt = g_counts[e];
    int m0 = mt * BM;
    if (m0 >= cnt) return;
    int n0 = blockIdx.x * BN;   // DIM/BN = 8 tiles
    int base = g_offsets[e];

    __shared__ float As[BKK][BM];
    __shared__ float Bs[BKK][BN];

    int tid = threadIdx.x;
    int tx = tid & 15;
    int ty = tid >> 4;
    float acc[8][8];
#pragma unroll
    for (int i = 0; i < 8; i++)
#pragma unroll
        for (int j = 0; j < 8; j++) acc[i][j] = 0.f;

    const float* wB = w2 + (size_t)e * HID * DIM;

    int arow = tid >> 1;
    int aseg = (tid & 1) * 4;
    int brow = tid >> 5;
    int bcol = (tid & 31) * 4;

    // clamp gathered row for tile remainder (reads stay in-bounds, stores guarded)
    int am = m0 + arow;
    size_t arowidx = (size_t)(base + ((am < cnt) ? am : (cnt - 1)));

    for (int k0 = 0; k0 < HID; k0 += BKK) {
        float4 av = *(const float4*)(g_H + arowidx * HID + k0 + aseg);
        As[aseg + 0][arow] = av.x;
        As[aseg + 1][arow] = av.y;
        As[aseg + 2][arow] = av.z;
        As[aseg + 3][arow] = av.w;
        float4 bv = *(const float4*)(wB + (size_t)(k0 + brow) * DIM + n0 + bcol);
        *(float4*)&Bs[brow][bcol] = bv;
        __syncthreads();
#pragma unroll
        for (int k = 0; k < BKK; k++) {
            float4 a0 = *(const float4*)&As[k][ty * 8];
            float4 a1 = *(const float4*)&As[k][ty * 8 + 4];
            float4 b0 = *(const float4*)&Bs[k][tx * 8];
            float4 b1v = *(const float4*)&Bs[k][tx * 8 + 4];
            float ra[8] = {a0.x, a0.y, a0.z, a0.w, a1.x, a1.y, a1.z, a1.w};
            float rb[8] = {b0.x, b0.y, b0.z, b0.w, b1v.x, b1v.y, b1v.z, b1v.w};
#pragma unroll
            for (int i = 0; i < 8; i++)
#pragma unroll
                for (int j = 0; j < 8; j++) acc[i][j] += ra[i] * rb[j];
        }
        __syncthreads();
    }

#pragma unroll
    for (int i = 0; i < 8; i++) {
        int m = m0 + ty * 8 + i;
        if (m >= cnt) continue;
        size_t obase = (size_t)(base + m) * DIM + n0 + tx * 8;
#pragma unroll
        for (int j = 0; j < 8; j++) g_Hout[obase + j] = acc[i][j];
    }
}

// ---------------- combine: out[t] = sum_k p_k * (Hout[row_k] + b2[e_k]) -----
__global__ void combine_kernel(const float* __restrict__ b2,
                               float* __restrict__ out) {
    int t = blockIdx.x;
    int e1 = g_topk_e[t * 2 + 0], e2 = g_topk_e[t * 2 + 1];
    float p1 = g_topk_p[t * 2 + 0], p2 = g_topk_p[t * 2 + 1];
    int r1 = g_tok_row[t * 2 + 0], r2 = g_tok_row[t * 2 + 1];
    const float* h1 = g_Hout + (size_t)r1 * DIM;
    const float* h2 = g_Hout + (size_t)r2 * DIM;
    const float* bb1 = b2 + (size_t)e1 * DIM;
    const float* bb2 = b2 + (size_t)e2 * DIM;
    for (int d = threadIdx.x; d < DIM; d += blockDim.x) {
        out[(size_t)t * DIM + d] = p1 * (h1[d] + bb1[d]) + p2 * (h2[d] + bb2[d]);
    }
}

// ---------------- launch ----------------------------------------------------
extern "C" void kernel_launch(void* const* d_in, const int* in_sizes, int n_in,
                              void* d_out, int out_size) {
    const float* x   = (const float*)d_in[0];
    const float* gw  = (const float*)d_in[1];
    const float* gb  = (const float*)d_in[2];
    const float* w1  = (const float*)d_in[3];
    const float* b1  = (const float*)d_in[4];
    const float* w2  = (const float*)d_in[5];
    const float* b2  = (const float*)d_in[6];
    float* out = (float*)d_out;

    init_kernel<<<1, 32>>>();
    gating_kernel<<<T / 8, 256>>>(x, gw, gb);     // 8 warps/block -> 4096 warps
    scan_kernel<<<1, 32>>>();
    assign_kernel<<<T / 256, 256>>>();
    gemm1_kernel<<<dim3(HID / BN, E * MT), 256>>>(x, w1, b1);
    gemm2_kernel<<<dim3(DIM / BN, E * MT), 256>>>(w2);
    combine_kernel<<<T, 256>>>(b2, out);
}

// round 7
// speedup vs baseline: 2.2266x; 2.2266x over previous
#include <cuda_runtime.h>
#include <cuda_bf16.h>

#define T    4096
#define DIM  1024
#define HID  4096
#define E    8
#define KTOP 2
#define NROW (T * KTOP)

#define BM 128
#define BN 128
#define BK 32
#define MT 32            // max M-tiles per expert

// SMEM layout per stage: A_hi[128][40h], A_lo, B_hi[32][136h], B_lo
#define PL_A     10240           // 128 * 80B
#define PL_B     8704            // 32 * 272B
#define OFF_AH   0
#define OFF_AL   PL_A
#define OFF_BH   (2 * PL_A)
#define OFF_BL   (2 * PL_A + PL_B)
#define STAGE_B  (2 * PL_A + 2 * PL_B)   // 37888
#define GEMM_SMEM (1024 + 2 * STAGE_B)   // 76800

// ---------------- static scratch (160 MB total: proven safe in R3) ----------
__device__ int   g_counts[E];
__device__ int   g_fill[E];
__device__ int   g_offsets[E + 1];
__device__ int   g_topk_e[T * KTOP];
__device__ float g_topk_p[T * KTOP];
__device__ int   g_row_token[NROW];
__device__ int   g_tok_row[T * KTOP];

__device__ __nv_bfloat16 g_Hhi[(size_t)NROW * HID];   // 64 MB
__device__ __nv_bfloat16 g_Hlo[(size_t)NROW * HID];   // 64 MB
__device__ float g_Hout[(size_t)NROW * DIM];          // 32 MB

// ---------------- PTX helpers ------------------------------------------------
__device__ __forceinline__ unsigned smem_u32(const void* p) {
    unsigned a;
    asm("{ .reg .u64 t; cvta.to.shared.u64 t, %1; cvt.u32.u64 %0, t; }" : "=r"(a) : "l"(p));
    return a;
}
__device__ __forceinline__ void ldsm4(unsigned* r, unsigned addr) {
    asm volatile("ldmatrix.sync.aligned.m8n8.x4.shared.b16 {%0,%1,%2,%3}, [%4];"
                 : "=r"(r[0]), "=r"(r[1]), "=r"(r[2]), "=r"(r[3]) : "r"(addr));
}
__device__ __forceinline__ void ldsm4t(unsigned* r, unsigned addr) {
    asm volatile("ldmatrix.sync.aligned.m8n8.x4.trans.shared.b16 {%0,%1,%2,%3}, [%4];"
                 : "=r"(r[0]), "=r"(r[1]), "=r"(r[2]), "=r"(r[3]) : "r"(addr));
}
__device__ __forceinline__ void mma16816(float* c, const unsigned* a, const unsigned* b) {
    asm volatile(
        "mma.sync.aligned.m16n8k16.row.col.f32.bf16.bf16.f32 "
        "{%0,%1,%2,%3}, {%4,%5,%6,%7}, {%8,%9}, {%0,%1,%2,%3};"
        : "+f"(c[0]), "+f"(c[1]), "+f"(c[2]), "+f"(c[3])
        : "r"(a[0]), "r"(a[1]), "r"(a[2]), "r"(a[3]), "r"(b[0]), "r"(b[1]));
}
// split two fp32 into packed bf16x2 hi and residual lo
__device__ __forceinline__ void split2(float a, float b, unsigned& hi, unsigned& lo) {
    __nv_bfloat16 ha = __float2bfloat16(a), hb = __float2bfloat16(b);
    __nv_bfloat162 H; H.x = ha; H.y = hb;
    hi = *(unsigned*)&H;
    __nv_bfloat162 L;
    L.x = __float2bfloat16(a - __bfloat162float(ha));
    L.y = __float2bfloat16(b - __bfloat162float(hb));
    lo = *(unsigned*)&L;
}

// ---------------- init -------------------------------------------------------
__global__ void init_kernel() {
    int i = threadIdx.x;
    if (i < E) { g_counts[i] = 0; g_fill[i] = 0; }
}

// ---------------- gating (exact fp32; one warp per token) --------------------
__global__ void gating_kernel(const float* __restrict__ x,
                              const float* __restrict__ gw,
                              const float* __restrict__ gb) {
    int warp = (blockIdx.x * blockDim.x + threadIdx.x) >> 5;
    int lane = threadIdx.x & 31;
    if (warp >= T) return;
    const float* xr = x + (size_t)warp * DIM;

    float acc[E];
#pragma unroll
    for (int e = 0; e < E; e++) acc[e] = 0.f;
    for (int d = lane; d < DIM; d += 32) {
        float xv = xr[d];
        float4 g0 = *(const float4*)(gw + d * E);
        float4 g1 = *(const float4*)(gw + d * E + 4);
        acc[0] += xv * g0.x; acc[1] += xv * g0.y;
        acc[2] += xv * g0.z; acc[3] += xv * g0.w;
        acc[4] += xv * g1.x; acc[5] += xv * g1.y;
        acc[6] += xv * g1.z; acc[7] += xv * g1.w;
    }
#pragma unroll
    for (int e = 0; e < E; e++)
#pragma unroll
        for (int off = 16; off > 0; off >>= 1)
            acc[e] += __shfl_down_sync(0xffffffffu, acc[e], off);

    if (lane == 0) {
        float lg[E];
        float m = -1e30f;
#pragma unroll
        for (int e = 0; e < E; e++) { lg[e] = acc[e] + gb[e]; m = fmaxf(m, lg[e]); }
        float s = 0.f;
#pragma unroll
        for (int e = 0; e < E; e++) { lg[e] = expf(lg[e] - m); s += lg[e]; }
        int e1 = 0;
#pragma unroll
        for (int e = 1; e < E; e++) if (lg[e] > lg[e1]) e1 = e;
        int e2 = (e1 == 0) ? 1 : 0;
#pragma unroll
        for (int e = 0; e < E; e++) if (e != e1 && e != e2 && lg[e] > lg[e2]) e2 = e;
        float inv = 1.0f / s;
        g_topk_e[warp * 2 + 0] = e1;
        g_topk_e[warp * 2 + 1] = e2;
        g_topk_p[warp * 2 + 0] = lg[e1] * inv;
        g_topk_p[warp * 2 + 1] = lg[e2] * inv;
        atomicAdd(&g_counts[e1], 1);
        atomicAdd(&g_counts[e2], 1);
    }
}

__global__ void scan_kernel() {
    if (threadIdx.x == 0) {
        int acc = 0;
        g_offsets[0] = 0;
        for (int e = 0; e < E; e++) { acc += g_counts[e]; g_offsets[e + 1] = acc; }
    }
}

__global__ void assign_kernel() {
    int t = blockIdx.x * blockDim.x + threadIdx.x;
    if (t >= T) return;
#pragma unroll
    for (int k = 0; k < KTOP; k++) {
        int e = g_topk_e[t * 2 + k];
        int slot = atomicAdd(&g_fill[e], 1);
        int row = g_offsets[e] + slot;
        g_row_token[row] = t;
        g_tok_row[t * 2 + k] = row;
    }
}

// ---------------- grouped HMMA GEMM (bf16x3 split, fp32 acc) -----------------
// G1: C[rows,HID] = gather(x fp32) @ w1[k][n], +b1, ReLU -> g_Hhi/g_Hlo
// G2: C[rows,DIM] = (Hhi,Hlo) @ w2[k][n]               -> g_Hout (fp32)
// fp32 sources are split to bf16 hi/lo during the STS phase (inline).
// 8 warps: 2 (m) x 4 (n); warp tile 64x32; 4x4 m16n8k16 frags; 3 plane combos.
template <int KD, int NTOT, bool G1>
__global__ void __launch_bounds__(256, 1)
moe_gemm(const float* __restrict__ xA,    // G1: x [T][DIM] fp32; G2: unused
         const float* __restrict__ wB,    // [E][KD][NTOT] fp32 (k-major rows)
         const float* __restrict__ bias) {
    int e  = blockIdx.y >> 5;
    int mt = blockIdx.y & 31;
    int cnt = g_counts[e];
    int m0 = mt * BM;
    if (m0 >= cnt) return;
    int n0 = blockIdx.x * BN;
    int base = g_offsets[e];

    extern __shared__ char smem[];
    int* toks = (int*)smem;
    char* tiles = smem + 1024;

    int tid  = threadIdx.x;
    int lane = tid & 31;
    int wid  = tid >> 5;

    if (G1 && tid < BM) {
        int m = m0 + tid;
        toks[tid] = g_row_token[base + (m < cnt ? m : cnt - 1)];
    }
    __syncthreads();

    // ---- load mapping: A: 2 threads/row (16 k each); B: 8 threads/k-row (16 n each)
    int arow = tid >> 1, kh = (tid & 1) * 16;
    int brow = tid >> 3, nh = (tid & 7) * 16;

    const float* aF = nullptr;
    const __nv_bfloat16 *aHh = nullptr, *aHl = nullptr;
    if (G1) {
        aF = xA + (size_t)toks[arow] * KD + kh;
    } else {
        int m = m0 + arow; if (m >= cnt) m = cnt - 1;
        aHh = g_Hhi + (size_t)(base + m) * KD + kh;
        aHl = g_Hlo + (size_t)(base + m) * KD + kh;
    }
    const float* bF = wB + ((size_t)e * KD + brow) * NTOT + n0 + nh;

    unsigned aoff = (unsigned)(arow * 80 + kh * 2);
    unsigned boff = (unsigned)(brow * 272 + nh * 2);

    // ---- staged registers
    float fa[16];            // G1 A fp32
    uint4 ha[2], la[2];      // G2 A bf16 planes
    float fb[16];            // B fp32

    auto ldg_stage = [&](int c) {
        int kk = c * BK;
        if (G1) {
#pragma unroll
            for (int q = 0; q < 4; q++)
                *(float4*)(fa + 4 * q) = __ldg((const float4*)(aF + kk + 4 * q));
        } else {
            ha[0] = __ldg((const uint4*)(aHh + kk));
            ha[1] = __ldg((const uint4*)(aHh + kk + 8));
            la[0] = __ldg((const uint4*)(aHl + kk));
            la[1] = __ldg((const uint4*)(aHl + kk + 8));
        }
        const float* bp = bF + (size_t)kk * NTOT;
#pragma unroll
        for (int q = 0; q < 4; q++)
            *(float4*)(fb + 4 * q) = __ldg((const float4*)(bp + 4 * q));
    };

    auto sts_stage = [&](int st) {
        char* stb = tiles + st * STAGE_B;
        if (G1) {
            unsigned h[8], l[8];
#pragma unroll
            for (int q = 0; q < 8; q++) split2(fa[2 * q], fa[2 * q + 1], h[q], l[q]);
            *(uint4*)(stb + OFF_AH + aoff)      = make_uint4(h[0], h[1], h[2], h[3]);
            *(uint4*)(stb + OFF_AH + aoff + 16) = make_uint4(h[4], h[5], h[6], h[7]);
            *(uint4*)(stb + OFF_AL + aoff)      = make_uint4(l[0], l[1], l[2], l[3]);
            *(uint4*)(stb + OFF_AL + aoff + 16) = make_uint4(l[4], l[5], l[6], l[7]);
        } else {
            *(uint4*)(stb + OFF_AH + aoff)      = ha[0];
            *(uint4*)(stb + OFF_AH + aoff + 16) = ha[1];
            *(uint4*)(stb + OFF_AL + aoff)      = la[0];
            *(uint4*)(stb + OFF_AL + aoff + 16) = la[1];
        }
        unsigned h[8], l[8];
#pragma unroll
        for (int q = 0; q < 8; q++) split2(fb[2 * q], fb[2 * q + 1], h[q], l[q]);
        *(uint4*)(stb + OFF_BH + boff)      = make_uint4(h[0], h[1], h[2], h[3]);
        *(uint4*)(stb + OFF_BH + boff + 16) = make_uint4(h[4], h[5], h[6], h[7]);
        *(uint4*)(stb + OFF_BL + boff)      = make_uint4(l[0], l[1], l[2], l[3]);
        *(uint4*)(stb + OFF_BL + boff + 16) = make_uint4(l[4], l[5], l[6], l[7]);
    };

    // ---- compute mapping
    int wm = wid >> 2;     // 0..1
    int wn = wid & 3;      // 0..3
    unsigned sbase = smem_u32(tiles);
    unsigned a_off = (unsigned)(((wm * 64 + (lane & 15)) * 40 + (lane >> 4) * 8) * 2);
    // B trans: lane i<16 -> row k0+i at col nb; lanes 16-31 -> same rows, col nb+8
    unsigned b_off = (unsigned)((lane & 15) * 272 + (wn * 32 + (lane >> 4) * 8) * 2);

    float acc[4][4][4];
#pragma unroll
    for (int i = 0; i < 4; i++)
#pragma unroll
        for (int j = 0; j < 4; j++)
#pragma unroll
            for (int q = 0; q < 4; q++) acc[i][j][q] = 0.f;

    auto compute_stage = [&](int st) {
        unsigned stb = sbase + st * STAGE_B;
#pragma unroll
        for (int ks = 0; ks < 2; ks++) {
            unsigned a_hi[4][4], a_lo[4][4], b_hi[4][2], b_lo[4][2];
#pragma unroll
            for (int i = 0; i < 4; i++) {
                unsigned ad = stb + a_off + (unsigned)(i * 16 * 80) + (unsigned)(ks * 32);
                ldsm4(a_hi[i], ad + OFF_AH);
                ldsm4(a_lo[i], ad + OFF_AL);
            }
#pragma unroll
            for (int jj = 0; jj < 2; jj++) {
                unsigned bd = stb + b_off + (unsigned)(ks * 16 * 272) + (unsigned)(jj * 32);
                unsigned th[4], tl[4];
                ldsm4t(th, bd + OFF_BH);
                ldsm4t(tl, bd + OFF_BL);
                b_hi[2 * jj][0] = th[0]; b_hi[2 * jj][1] = th[1];
                b_hi[2 * jj + 1][0] = th[2]; b_hi[2 * jj + 1][1] = th[3];
                b_lo[2 * jj][0] = tl[0]; b_lo[2 * jj][1] = tl[1];
                b_lo[2 * jj + 1][0] = tl[2]; b_lo[2 * jj + 1][1] = tl[3];
            }
#pragma unroll
            for (int i = 0; i < 4; i++)
#pragma unroll
                for (int j = 0; j < 4; j++) {
                    mma16816(acc[i][j], a_hi[i], b_hi[j]);
                    mma16816(acc[i][j], a_hi[i], b_lo[j]);
                    mma16816(acc[i][j], a_lo[i], b_hi[j]);
                }
        }
    };

    const int NC = KD / BK;
    ldg_stage(0);
    sts_stage(0);
    __syncthreads();
    for (int c = 0; c < NC; c++) {
        if (c + 1 < NC) ldg_stage(c + 1);
        compute_stage(c & 1);
        if (c + 1 < NC) sts_stage((c + 1) & 1);
        __syncthreads();
    }

    // ---- epilogue
    int r_base = wm * 64 + (lane >> 2);
    int c_base = n0 + wn * 32 + 2 * (lane & 3);
#pragma unroll
    for (int i = 0; i < 4; i++) {
#pragma unroll
        for (int h = 0; h < 2; h++) {
            int m = m0 + r_base + i * 16 + h * 8;
            if (m >= cnt) continue;
            size_t orow = (size_t)(base + m);
#pragma unroll
            for (int j = 0; j < 4; j++) {
                int n = c_base + j * 8;
                float v0 = acc[i][j][h * 2];
                float v1 = acc[i][j][h * 2 + 1];
                if (G1) {
                    v0 += __ldg(&bias[(size_t)e * NTOT + n]);
                    v1 += __ldg(&bias[(size_t)e * NTOT + n + 1]);
                    v0 = fmaxf(v0, 0.f); v1 = fmaxf(v1, 0.f);
                    unsigned hh, ll;
                    split2(v0, v1, hh, ll);
                    *(unsigned*)(g_Hhi + orow * HID + n) = hh;
                    *(unsigned*)(g_Hlo + orow * HID + n) = ll;
                } else {
                    float2 v; v.x = v0; v.y = v1;
                    *(float2*)(g_Hout + orow * DIM + n) = v;
                }
            }
        }
    }
}

// ---------------- combine ----------------------------------------------------
__global__ void combine_kernel(const float* __restrict__ b2,
                               float* __restrict__ out) {
    int t = blockIdx.x;
    int e1 = g_topk_e[t * 2 + 0], e2 = g_topk_e[t * 2 + 1];
    float p1 = g_topk_p[t * 2 + 0], p2 = g_topk_p[t * 2 + 1];
    int r1 = g_tok_row[t * 2 + 0], r2 = g_tok_row[t * 2 + 1];
    const float* h1 = g_Hout + (size_t)r1 * DIM;
    const float* h2 = g_Hout + (size_t)r2 * DIM;
    const float* bb1 = b2 + (size_t)e1 * DIM;
    const float* bb2 = b2 + (size_t)e2 * DIM;
    for (int d = threadIdx.x; d < DIM; d += blockDim.x) {
        out[(size_t)t * DIM + d] = p1 * (h1[d] + bb1[d]) + p2 * (h2[d] + bb2[d]);
    }
}

// ---------------- launch -----------------------------------------------------
extern "C" void kernel_launch(void* const* d_in, const int* in_sizes, int n_in,
                              void* d_out, int out_size) {
    (void)in_sizes; (void)n_in; (void)out_size;
    const float* x  = (const float*)d_in[0];
    const float* gw = (const float*)d_in[1];
    const float* gb = (const float*)d_in[2];
    const float* w1 = (const float*)d_in[3];
    const float* b1 = (const float*)d_in[4];
    const float* w2 = (const float*)d_in[5];
    const float* b2 = (const float*)d_in[6];
    float* out = (float*)d_out;

    cudaFuncSetAttribute((const void*)moe_gemm<DIM, HID, true>,
                         cudaFuncAttributeMaxDynamicSharedMemorySize, GEMM_SMEM);
    cudaFuncSetAttribute((const void*)moe_gemm<HID, DIM, false>,
                         cudaFuncAttributeMaxDynamicSharedMemorySize, GEMM_SMEM);

    init_kernel<<<1, 32>>>();
    gating_kernel<<<T / 8, 256>>>(x, gw, gb);
    scan_kernel<<<1, 32>>>();
    assign_kernel<<<T / 256, 256>>>();

    moe_gemm<DIM, HID, true><<<dim3(HID / BN, E * MT), 256, GEMM_SMEM>>>(x, w1, b1);
    moe_gemm<HID, DIM, false><<<dim3(DIM / BN, E * MT), 256, GEMM_SMEM>>>(x, w2, b2);

    combine_kernel<<<T, 256>>>(b2, out);
}

// round 8
// speedup vs baseline: 2.3026x; 1.0341x over previous
#include <cuda_runtime.h>
#include <cuda_bf16.h>

#define T    4096
#define DIM  1024
#define HID  4096
#define E    8
#define KTOP 2
#define NROW (T * KTOP)

#define BM 128
#define BN 128
#define BK 32
#define MT 32            // max M-tiles per expert
#define NTHR 512         // 16 warps: 4 (m) x 4 (n), warp tile 32x32

// SMEM layout per stage: A_hi[128][40h], A_lo, B_hi[32][136h], B_lo
#define PL_A     10240           // 128 * 80B
#define PL_B     8704            // 32 * 272B
#define OFF_AH   0
#define OFF_AL   PL_A
#define OFF_BH   (2 * PL_A)
#define OFF_BL   (2 * PL_A + PL_B)
#define STAGE_B  (2 * PL_A + 2 * PL_B)   // 37888
#define GEMM_SMEM (1024 + 2 * STAGE_B)   // 76800

// ---------------- static scratch (160 MB total: proven safe) -----------------
__device__ int   g_counts[E];
__device__ int   g_fill[E];
__device__ int   g_offsets[E + 1];
__device__ int   g_topk_e[T * KTOP];
__device__ float g_topk_p[T * KTOP];
__device__ int   g_row_token[NROW];
__device__ int   g_tok_row[T * KTOP];

__device__ __nv_bfloat16 g_Hhi[(size_t)NROW * HID];   // 64 MB
__device__ __nv_bfloat16 g_Hlo[(size_t)NROW * HID];   // 64 MB
__device__ float g_Hout[(size_t)NROW * DIM];          // 32 MB

// ---------------- PTX helpers ------------------------------------------------
__device__ __forceinline__ unsigned smem_u32(const void* p) {
    unsigned a;
    asm("{ .reg .u64 t; cvta.to.shared.u64 t, %1; cvt.u32.u64 %0, t; }" : "=r"(a) : "l"(p));
    return a;
}
__device__ __forceinline__ void ldsm4(unsigned* r, unsigned addr) {
    asm volatile("ldmatrix.sync.aligned.m8n8.x4.shared.b16 {%0,%1,%2,%3}, [%4];"
                 : "=r"(r[0]), "=r"(r[1]), "=r"(r[2]), "=r"(r[3]) : "r"(addr));
}
__device__ __forceinline__ void ldsm4t(unsigned* r, unsigned addr) {
    asm volatile("ldmatrix.sync.aligned.m8n8.x4.trans.shared.b16 {%0,%1,%2,%3}, [%4];"
                 : "=r"(r[0]), "=r"(r[1]), "=r"(r[2]), "=r"(r[3]) : "r"(addr));
}
__device__ __forceinline__ void mma16816(float* c, const unsigned* a, const unsigned* b) {
    asm volatile(
        "mma.sync.aligned.m16n8k16.row.col.f32.bf16.bf16.f32 "
        "{%0,%1,%2,%3}, {%4,%5,%6,%7}, {%8,%9}, {%0,%1,%2,%3};"
        : "+f"(c[0]), "+f"(c[1]), "+f"(c[2]), "+f"(c[3])
        : "r"(a[0]), "r"(a[1]), "r"(a[2]), "r"(a[3]), "r"(b[0]), "r"(b[1]));
}
// split two fp32 into packed bf16x2 hi and residual lo
__device__ __forceinline__ void split2(float a, float b, unsigned& hi, unsigned& lo) {
    __nv_bfloat16 ha = __float2bfloat16(a), hb = __float2bfloat16(b);
    __nv_bfloat162 H; H.x = ha; H.y = hb;
    hi = *(unsigned*)&H;
    __nv_bfloat162 L;
    L.x = __float2bfloat16(a - __bfloat162float(ha));
    L.y = __float2bfloat16(b - __bfloat162float(hb));
    lo = *(unsigned*)&L;
}

// ---------------- init -------------------------------------------------------
__global__ void init_kernel() {
    int i = threadIdx.x;
    if (i < E) { g_counts[i] = 0; g_fill[i] = 0; }
}

// ---------------- gating (exact fp32; one warp per token) --------------------
__global__ void gating_kernel(const float* __restrict__ x,
                              const float* __restrict__ gw,
                              const float* __restrict__ gb) {
    int warp = (blockIdx.x * blockDim.x + threadIdx.x) >> 5;
    int lane = threadIdx.x & 31;
    if (warp >= T) return;
    const float* xr = x + (size_t)warp * DIM;

    float acc[E];
#pragma unroll
    for (int e = 0; e < E; e++) acc[e] = 0.f;
    for (int d = lane; d < DIM; d += 32) {
        float xv = xr[d];
        float4 g0 = *(const float4*)(gw + d * E);
        float4 g1 = *(const float4*)(gw + d * E + 4);
        acc[0] += xv * g0.x; acc[1] += xv * g0.y;
        acc[2] += xv * g0.z; acc[3] += xv * g0.w;
        acc[4] += xv * g1.x; acc[5] += xv * g1.y;
        acc[6] += xv * g1.z; acc[7] += xv * g1.w;
    }
#pragma unroll
    for (int e = 0; e < E; e++)
#pragma unroll
        for (int off = 16; off > 0; off >>= 1)
            acc[e] += __shfl_down_sync(0xffffffffu, acc[e], off);

    if (lane == 0) {
        float lg[E];
        float m = -1e30f;
#pragma unroll
        for (int e = 0; e < E; e++) { lg[e] = acc[e] + gb[e]; m = fmaxf(m, lg[e]); }
        float s = 0.f;
#pragma unroll
        for (int e = 0; e < E; e++) { lg[e] = expf(lg[e] - m); s += lg[e]; }
        int e1 = 0;
#pragma unroll
        for (int e = 1; e < E; e++) if (lg[e] > lg[e1]) e1 = e;
        int e2 = (e1 == 0) ? 1 : 0;
#pragma unroll
        for (int e = 0; e < E; e++) if (e != e1 && e != e2 && lg[e] > lg[e2]) e2 = e;
        float inv = 1.0f / s;
        g_topk_e[warp * 2 + 0] = e1;
        g_topk_e[warp * 2 + 1] = e2;
        g_topk_p[warp * 2 + 0] = lg[e1] * inv;
        g_topk_p[warp * 2 + 1] = lg[e2] * inv;
        atomicAdd(&g_counts[e1], 1);
        atomicAdd(&g_counts[e2], 1);
    }
}

__global__ void scan_kernel() {
    if (threadIdx.x == 0) {
        int acc = 0;
        g_offsets[0] = 0;
        for (int e = 0; e < E; e++) { acc += g_counts[e]; g_offsets[e + 1] = acc; }
    }
}

__global__ void assign_kernel() {
    int t = blockIdx.x * blockDim.x + threadIdx.x;
    if (t >= T) return;
#pragma unroll
    for (int k = 0; k < KTOP; k++) {
        int e = g_topk_e[t * 2 + k];
        int slot = atomicAdd(&g_fill[e], 1);
        int row = g_offsets[e] + slot;
        g_row_token[row] = t;
        g_tok_row[t * 2 + k] = row;
    }
}

// ---------------- grouped HMMA GEMM (bf16x3 split, fp32 acc) -----------------
// G1: C[rows,HID] = gather(x fp32) @ w1[k][n], +b1, ReLU -> g_Hhi/g_Hlo
// G2: C[rows,DIM] = (Hhi,Hlo) @ w2[k][n]               -> g_Hout (fp32)
// 16 warps: 4 (m) x 4 (n); warp tile 32x32; 2x4 m16n8k16 frags; 3 plane combos.
template <int KD, int NTOT, bool G1>
__global__ void __launch_bounds__(NTHR, 1)
moe_gemm(const float* __restrict__ xA,    // G1: x [T][DIM] fp32; G2: unused
         const float* __restrict__ wB,    // [E][KD][NTOT] fp32 (k-major rows)
         const float* __restrict__ bias) {
    int e  = blockIdx.y >> 5;
    int mt = blockIdx.y & 31;
    int cnt = g_counts[e];
    int m0 = mt * BM;
    if (m0 >= cnt) return;
    int n0 = blockIdx.x * BN;
    int base = g_offsets[e];

    extern __shared__ char smem[];
    int* toks = (int*)smem;
    char* tiles = smem + 1024;

    int tid  = threadIdx.x;
    int lane = tid & 31;
    int wid  = tid >> 5;

    if (G1 && tid < BM) {
        int m = m0 + tid;
        toks[tid] = g_row_token[base + (m < cnt ? m : cnt - 1)];
    }
    __syncthreads();

    // ---- load mapping: A: 4 threads/row (8 k each); B: 16 threads/k-row (8 n each)
    int arow = tid >> 2, kh = (tid & 3) * 8;
    int brow = tid >> 4, nh = (tid & 15) * 8;

    const float* aF = nullptr;
    const __nv_bfloat16 *aHh = nullptr, *aHl = nullptr;
    if (G1) {
        aF = xA + (size_t)toks[arow] * KD + kh;
    } else {
        int m = m0 + arow; if (m >= cnt) m = cnt - 1;
        aHh = g_Hhi + (size_t)(base + m) * KD + kh;
        aHl = g_Hlo + (size_t)(base + m) * KD + kh;
    }
    const float* bF = wB + ((size_t)e * KD + brow) * NTOT + n0 + nh;

    unsigned aoff = (unsigned)(arow * 80 + kh * 2);
    unsigned boff = (unsigned)(brow * 272 + nh * 2);

    // ---- staged registers (8 floats A, 8 floats B; G2 A already split)
    float fa[8];
    uint4 ha, la;
    float fb[8];

    auto ldg_stage = [&](int c) {
        int kk = c * BK;
        if (G1) {
            *(float4*)(fa)     = __ldg((const float4*)(aF + kk));
            *(float4*)(fa + 4) = __ldg((const float4*)(aF + kk + 4));
        } else {
            ha = __ldg((const uint4*)(aHh + kk));
            la = __ldg((const uint4*)(aHl + kk));
        }
        const float* bp = bF + (size_t)kk * NTOT;
        *(float4*)(fb)     = __ldg((const float4*)(bp));
        *(float4*)(fb + 4) = __ldg((const float4*)(bp + 4));
    };

    auto sts_stage = [&](int st) {
        char* stb = tiles + st * STAGE_B;
        if (G1) {
            unsigned h[4], l[4];
#pragma unroll
            for (int q = 0; q < 4; q++) split2(fa[2 * q], fa[2 * q + 1], h[q], l[q]);
            *(uint4*)(stb + OFF_AH + aoff) = make_uint4(h[0], h[1], h[2], h[3]);
            *(uint4*)(stb + OFF_AL + aoff) = make_uint4(l[0], l[1], l[2], l[3]);
        } else {
            *(uint4*)(stb + OFF_AH + aoff) = ha;
            *(uint4*)(stb + OFF_AL + aoff) = la;
        }
        unsigned h[4], l[4];
#pragma unroll
        for (int q = 0; q < 4; q++) split2(fb[2 * q], fb[2 * q + 1], h[q], l[q]);
        *(uint4*)(stb + OFF_BH + boff) = make_uint4(h[0], h[1], h[2], h[3]);
        *(uint4*)(stb + OFF_BL + boff) = make_uint4(l[0], l[1], l[2], l[3]);
    };

    // ---- compute mapping: warp (wm, wn) owns 32x32
    int wm = wid >> 2;     // 0..3
    int wn = wid & 3;      // 0..3
    unsigned sbase = smem_u32(tiles);
    unsigned a_off = (unsigned)(((wm * 32 + (lane & 15)) * 40 + (lane >> 4) * 8) * 2);
    unsigned b_off = (unsigned)((lane & 15) * 272 + (wn * 32 + (lane >> 4) * 8) * 2);

    float acc[2][4][4];
#pragma unroll
    for (int i = 0; i < 2; i++)
#pragma unroll
        for (int j = 0; j < 4; j++)
#pragma unroll
            for (int q = 0; q < 4; q++) acc[i][j][q] = 0.f;

    auto compute_stage = [&](int st) {
        unsigned stb = sbase + st * STAGE_B;
#pragma unroll
        for (int ks = 0; ks < 2; ks++) {
            unsigned a_hi[2][4], a_lo[2][4], b_hi[4][2], b_lo[4][2];
#pragma unroll
            for (int i = 0; i < 2; i++) {
                unsigned ad = stb + a_off + (unsigned)(i * 16 * 80) + (unsigned)(ks * 32);
                ldsm4(a_hi[i], ad + OFF_AH);
                ldsm4(a_lo[i], ad + OFF_AL);
            }
#pragma unroll
            for (int jj = 0; jj < 2; jj++) {
                unsigned bd = stb + b_off + (unsigned)(ks * 16 * 272) + (unsigned)(jj * 32);
                unsigned th[4], tl[4];
                ldsm4t(th, bd + OFF_BH);
                ldsm4t(tl, bd + OFF_BL);
                b_hi[2 * jj][0] = th[0]; b_hi[2 * jj][1] = th[1];
                b_hi[2 * jj + 1][0] = th[2]; b_hi[2 * jj + 1][1] = th[3];
                b_lo[2 * jj][0] = tl[0]; b_lo[2 * jj][1] = tl[1];
                b_lo[2 * jj + 1][0] = tl[2]; b_lo[2 * jj + 1][1] = tl[3];
            }
#pragma unroll
            for (int i = 0; i < 2; i++)
#pragma unroll
                for (int j = 0; j < 4; j++) {
                    mma16816(acc[i][j], a_hi[i], b_hi[j]);
                    mma16816(acc[i][j], a_hi[i], b_lo[j]);
                    mma16816(acc[i][j], a_lo[i], b_hi[j]);
                }
        }
    };

    const int NC = KD / BK;
    ldg_stage(0);
    sts_stage(0);
    __syncthreads();
    for (int c = 0; c < NC; c++) {
        if (c + 1 < NC) ldg_stage(c + 1);
        compute_stage(c & 1);
        if (c + 1 < NC) sts_stage((c + 1) & 1);
        __syncthreads();
    }

    // ---- epilogue
    int r_base = wm * 32 + (lane >> 2);
    int c_base = n0 + wn * 32 + 2 * (lane & 3);
#pragma unroll
    for (int i = 0; i < 2; i++) {
#pragma unroll
        for (int h = 0; h < 2; h++) {
            int m = m0 + r_base + i * 16 + h * 8;
            if (m >= cnt) continue;
            size_t orow = (size_t)(base + m);
#pragma unroll
            for (int j = 0; j < 4; j++) {
                int n = c_base + j * 8;
                float v0 = acc[i][j][h * 2];
                float v1 = acc[i][j][h * 2 + 1];
                if (G1) {
                    v0 += __ldg(&bias[(size_t)e * NTOT + n]);
                    v1 += __ldg(&bias[(size_t)e * NTOT + n + 1]);
                    v0 = fmaxf(v0, 0.f); v1 = fmaxf(v1, 0.f);
                    unsigned hh, ll;
                    split2(v0, v1, hh, ll);
                    *(unsigned*)(g_Hhi + orow * HID + n) = hh;
                    *(unsigned*)(g_Hlo + orow * HID + n) = ll;
                } else {
                    float2 v; v.x = v0; v.y = v1;
                    *(float2*)(g_Hout + orow * DIM + n) = v;
                }
            }
        }
    }
}

// ---------------- combine ----------------------------------------------------
__global__ void combine_kernel(const float* __restrict__ b2,
                               float* __restrict__ out) {
    int t = blockIdx.x;
    int e1 = g_topk_e[t * 2 + 0], e2 = g_topk_e[t * 2 + 1];
    float p1 = g_topk_p[t * 2 + 0], p2 = g_topk_p[t * 2 + 1];
    int r1 = g_tok_row[t * 2 + 0], r2 = g_tok_row[t * 2 + 1];
    const float* h1 = g_Hout + (size_t)r1 * DIM;
    const float* h2 = g_Hout + (size_t)r2 * DIM;
    const float* bb1 = b2 + (size_t)e1 * DIM;
    const float* bb2 = b2 + (size_t)e2 * DIM;
    for (int d = threadIdx.x; d < DIM; d += blockDim.x) {
        out[(size_t)t * DIM + d] = p1 * (h1[d] + bb1[d]) + p2 * (h2[d] + bb2[d]);
    }
}

// ---------------- launch -----------------------------------------------------
extern "C" void kernel_launch(void* const* d_in, const int* in_sizes, int n_in,
                              void* d_out, int out_size) {
    (void)in_sizes; (void)n_in; (void)out_size;
    const float* x  = (const float*)d_in[0];
    const float* gw = (const float*)d_in[1];
    const float* gb = (const float*)d_in[2];
    const float* w1 = (const float*)d_in[3];
    const float* b1 = (const float*)d_in[4];
    const float* w2 = (const float*)d_in[5];
    const float* b2 = (const float*)d_in[6];
    float* out = (float*)d_out;

    cudaFuncSetAttribute((const void*)moe_gemm<DIM, HID, true>,
                         cudaFuncAttributeMaxDynamicSharedMemorySize, GEMM_SMEM);
    cudaFuncSetAttribute((const void*)moe_gemm<HID, DIM, false>,
                         cudaFuncAttributeMaxDynamicSharedMemorySize, GEMM_SMEM);

    init_kernel<<<1, 32>>>();
    gating_kernel<<<T / 8, 256>>>(x, gw, gb);
    scan_kernel<<<1, 32>>>();
    assign_kernel<<<T / 256, 256>>>();

    moe_gemm<DIM, HID, true><<<dim3(HID / BN, E * MT), NTHR, GEMM_SMEM>>>(x, w1, b1);
    moe_gemm<HID, DIM, false><<<dim3(DIM / BN, E * MT), NTHR, GEMM_SMEM>>>(x, w2, b2);

    combine_kernel<<<T, 256>>>(b2, out);
}

// round 9
// speedup vs baseline: 3.2953x; 1.4312x over previous
#include <cuda_runtime.h>
#include <cuda_fp16.h>

#define T    4096
#define DIM  1024
#define HID  4096
#define E    8
#define KTOP 2
#define NROW (T * KTOP)

#define BM 128
#define BN 128
#define BK 32
#define MT 32            // max M-tiles per expert
#define NTHR 512         // 16 warps: 4 (m) x 4 (n), warp tile 32x32

// SMEM layout per stage: A_hi[128][40h], A_lo[128][40h], B[32][136h]
#define PL_A     10240           // 128 * 80B
#define PL_B     8704            // 32 * 272B
#define OFF_AH   0
#define OFF_AL   PL_A
#define OFF_B    (2 * PL_A)
#define STAGE_B  (2 * PL_A + PL_B)       // 29184
#define GEMM_SMEM (1024 + 2 * STAGE_B)   // 59392

// ---------------- static scratch (160 MB total: proven safe) -----------------
__device__ int   g_counts[E];
__device__ int   g_fill[E];
__device__ int   g_offsets[E + 1];
__device__ int   g_topk_e[T * KTOP];
__device__ float g_topk_p[T * KTOP];
__device__ int   g_row_token[NROW];
__device__ int   g_tok_row[T * KTOP];

__device__ __half g_Hhi[(size_t)NROW * HID];   // 64 MB
__device__ __half g_Hlo[(size_t)NROW * HID];   // 64 MB
__device__ float  g_Hout[(size_t)NROW * DIM];  // 32 MB

// ---------------- PTX helpers ------------------------------------------------
__device__ __forceinline__ unsigned smem_u32(const void* p) {
    unsigned a;
    asm("{ .reg .u64 t; cvta.to.shared.u64 t, %1; cvt.u32.u64 %0, t; }" : "=r"(a) : "l"(p));
    return a;
}
__device__ __forceinline__ void ldsm4(unsigned* r, unsigned addr) {
    asm volatile("ldmatrix.sync.aligned.m8n8.x4.shared.b16 {%0,%1,%2,%3}, [%4];"
                 : "=r"(r[0]), "=r"(r[1]), "=r"(r[2]), "=r"(r[3]) : "r"(addr));
}
__device__ __forceinline__ void ldsm4t(unsigned* r, unsigned addr) {
    asm volatile("ldmatrix.sync.aligned.m8n8.x4.trans.shared.b16 {%0,%1,%2,%3}, [%4];"
                 : "=r"(r[0]), "=r"(r[1]), "=r"(r[2]), "=r"(r[3]) : "r"(addr));
}
__device__ __forceinline__ void mma16816(float* c, const unsigned* a, const unsigned* b) {
    asm volatile(
        "mma.sync.aligned.m16n8k16.row.col.f32.f16.f16.f32 "
        "{%0,%1,%2,%3}, {%4,%5,%6,%7}, {%8,%9}, {%0,%1,%2,%3};"
        : "+f"(c[0]), "+f"(c[1]), "+f"(c[2]), "+f"(c[3])
        : "r"(a[0]), "r"(a[1]), "r"(a[2]), "r"(a[3]), "r"(b[0]), "r"(b[1]));
}
// split two fp32 into packed fp16x2 hi and residual lo
__device__ __forceinline__ void split2h(float a, float b, unsigned& hi, unsigned& lo) {
    __half ha = __float2half_rn(a), hb = __float2half_rn(b);
    __half2 H = __halves2half2(ha, hb);
    hi = *(unsigned*)&H;
    __half2 L = __halves2half2(__float2half_rn(a - __half2float(ha)),
                               __float2half_rn(b - __half2float(hb)));
    lo = *(unsigned*)&L;
}
// round two fp32 into packed fp16x2
__device__ __forceinline__ unsigned pack2h(float a, float b) {
    __half2 H = __halves2half2(__float2half_rn(a), __float2half_rn(b));
    return *(unsigned*)&H;
}

// ---------------- init -------------------------------------------------------
__global__ void init_kernel() {
    int i = threadIdx.x;
    if (i < E) { g_counts[i] = 0; g_fill[i] = 0; }
}

// ---------------- gating (exact fp32; one warp per token) --------------------
__global__ void gating_kernel(const float* __restrict__ x,
                              const float* __restrict__ gw,
                              const float* __restrict__ gb) {
    int warp = (blockIdx.x * blockDim.x + threadIdx.x) >> 5;
    int lane = threadIdx.x & 31;
    if (warp >= T) return;
    const float* xr = x + (size_t)warp * DIM;

    float acc[E];
#pragma unroll
    for (int e = 0; e < E; e++) acc[e] = 0.f;
    for (int d = lane; d < DIM; d += 32) {
        float xv = xr[d];
        float4 g0 = *(const float4*)(gw + d * E);
        float4 g1 = *(const float4*)(gw + d * E + 4);
        acc[0] += xv * g0.x; acc[1] += xv * g0.y;
        acc[2] += xv * g0.z; acc[3] += xv * g0.w;
        acc[4] += xv * g1.x; acc[5] += xv * g1.y;
        acc[6] += xv * g1.z; acc[7] += xv * g1.w;
    }
#pragma unroll
    for (int e = 0; e < E; e++)
#pragma unroll
        for (int off = 16; off > 0; off >>= 1)
            acc[e] += __shfl_down_sync(0xffffffffu, acc[e], off);

    if (lane == 0) {
        float lg[E];
        float m = -1e30f;
#pragma unroll
        for (int e = 0; e < E; e++) { lg[e] = acc[e] + gb[e]; m = fmaxf(m, lg[e]); }
        float s = 0.f;
#pragma unroll
        for (int e = 0; e < E; e++) { lg[e] = expf(lg[e] - m); s += lg[e]; }
        int e1 = 0;
#pragma unroll
        for (int e = 1; e < E; e++) if (lg[e] > lg[e1]) e1 = e;
        int e2 = (e1 == 0) ? 1 : 0;
#pragma unroll
        for (int e = 0; e < E; e++) if (e != e1 && e != e2 && lg[e] > lg[e2]) e2 = e;
        float inv = 1.0f / s;
        g_topk_e[warp * 2 + 0] = e1;
        g_topk_e[warp * 2 + 1] = e2;
        g_topk_p[warp * 2 + 0] = lg[e1] * inv;
        g_topk_p[warp * 2 + 1] = lg[e2] * inv;
        atomicAdd(&g_counts[e1], 1);
        atomicAdd(&g_counts[e2], 1);
    }
}

__global__ void scan_kernel() {
    if (threadIdx.x == 0) {
        int acc = 0;
        g_offsets[0] = 0;
        for (int e = 0; e < E; e++) { acc += g_counts[e]; g_offsets[e + 1] = acc; }
    }
}

__global__ void assign_kernel() {
    int t = blockIdx.x * blockDim.x + threadIdx.x;
    if (t >= T) return;
#pragma unroll
    for (int k = 0; k < KTOP; k++) {
        int e = g_topk_e[t * 2 + k];
        int slot = atomicAdd(&g_fill[e], 1);
        int row = g_offsets[e] + slot;
        g_row_token[row] = t;
        g_tok_row[t * 2 + k] = row;
    }
}

// ---------------- grouped HMMA GEMM (fp16 split-A, fp16 B, fp32 acc) ---------
// C = (A_hi + A_lo) @ B_h ; error = fp16 rounding of B (~2e-4), budget 1e-3.
// G1: A = gather(x) split inline; +b1, ReLU -> g_Hhi/g_Hlo (fp16 planes)
// G2: A = (Hhi,Hlo); -> g_Hout fp32
// 16 warps: 4 (m) x 4 (n); warp tile 32x32; 2 MMAs per frag pair.
template <int KD, int NTOT, bool G1>
__global__ void __launch_bounds__(NTHR, 1)
moe_gemm(const float* __restrict__ xA,
         const float* __restrict__ wB,    // [E][KD][NTOT] fp32 (k-major rows)
         const float* __restrict__ bias) {
    int e  = blockIdx.y >> 5;
    int mt = blockIdx.y & 31;
    int cnt = g_counts[e];
    int m0 = mt * BM;
    if (m0 >= cnt) return;
    int n0 = blockIdx.x * BN;
    int base = g_offsets[e];

    extern __shared__ char smem[];
    int* toks = (int*)smem;
    char* tiles = smem + 1024;

    int tid  = threadIdx.x;
    int lane = tid & 31;
    int wid  = tid >> 5;

    if (G1 && tid < BM) {
        int m = m0 + tid;
        toks[tid] = g_row_token[base + (m < cnt ? m : cnt - 1)];
    }
    __syncthreads();

    // ---- load mapping: A: 4 threads/row (8 k each); B: 16 threads/k-row (8 n each)
    int arow = tid >> 2, kh = (tid & 3) * 8;
    int brow = tid >> 4, nh = (tid & 15) * 8;

    const float* aF = nullptr;
    const __half *aHh = nullptr, *aHl = nullptr;
    if (G1) {
        aF = xA + (size_t)toks[arow] * KD + kh;
    } else {
        int m = m0 + arow; if (m >= cnt) m = cnt - 1;
        aHh = g_Hhi + (size_t)(base + m) * KD + kh;
        aHl = g_Hlo + (size_t)(base + m) * KD + kh;
    }
    const float* bF = wB + ((size_t)e * KD + brow) * NTOT + n0 + nh;

    unsigned aoff = (unsigned)(arow * 80 + kh * 2);
    unsigned boff = (unsigned)(brow * 272 + nh * 2);

    // ---- staged registers
    float fa[8];
    uint4 ha, la;
    float fb[8];

    auto ldg_stage = [&](int c) {
        int kk = c * BK;
        if (G1) {
            *(float4*)(fa)     = __ldg((const float4*)(aF + kk));
            *(float4*)(fa + 4) = __ldg((const float4*)(aF + kk + 4));
        } else {
            ha = __ldg((const uint4*)(aHh + kk));
            la = __ldg((const uint4*)(aHl + kk));
        }
        const float* bp = bF + (size_t)kk * NTOT;
        *(float4*)(fb)     = __ldg((const float4*)(bp));
        *(float4*)(fb + 4) = __ldg((const float4*)(bp + 4));
    };

    auto sts_stage = [&](int st) {
        char* stb = tiles + st * STAGE_B;
        if (G1) {
            unsigned h[4], l[4];
#pragma unroll
            for (int q = 0; q < 4; q++) split2h(fa[2 * q], fa[2 * q + 1], h[q], l[q]);
            *(uint4*)(stb + OFF_AH + aoff) = make_uint4(h[0], h[1], h[2], h[3]);
            *(uint4*)(stb + OFF_AL + aoff) = make_uint4(l[0], l[1], l[2], l[3]);
        } else {
            *(uint4*)(stb + OFF_AH + aoff) = ha;
            *(uint4*)(stb + OFF_AL + aoff) = la;
        }
        unsigned h[4];
#pragma unroll
        for (int q = 0; q < 4; q++) h[q] = pack2h(fb[2 * q], fb[2 * q + 1]);
        *(uint4*)(stb + OFF_B + boff) = make_uint4(h[0], h[1], h[2], h[3]);
    };

    // ---- compute mapping: warp (wm, wn) owns 32x32
    int wm = wid >> 2;     // 0..3
    int wn = wid & 3;      // 0..3
    unsigned sbase = smem_u32(tiles);
    unsigned a_off = (unsigned)(((wm * 32 + (lane & 15)) * 40 + (lane >> 4) * 8) * 2);
    unsigned b_off = (unsigned)((lane & 15) * 272 + (wn * 32 + (lane >> 4) * 8) * 2);

    float acc[2][4][4];
#pragma unroll
    for (int i = 0; i < 2; i++)
#pragma unroll
        for (int j = 0; j < 4; j++)
#pragma unroll
            for (int q = 0; q < 4; q++) acc[i][j][q] = 0.f;

    auto compute_stage = [&](int st) {
        unsigned stb = sbase + st * STAGE_B;
#pragma unroll
        for (int ks = 0; ks < 2; ks++) {
            unsigned a_hi[2][4], a_lo[2][4], bfr[4][2];
#pragma unroll
            for (int i = 0; i < 2; i++) {
                unsigned ad = stb + a_off + (unsigned)(i * 16 * 80) + (unsigned)(ks * 32);
                ldsm4(a_hi[i], ad + OFF_AH);
                ldsm4(a_lo[i], ad + OFF_AL);
            }
#pragma unroll
            for (int jj = 0; jj < 2; jj++) {
                unsigned bd = stb + b_off + (unsigned)(ks * 16 * 272) + (unsigned)(jj * 32);
                unsigned th[4];
                ldsm4t(th, bd + OFF_B);
                bfr[2 * jj][0] = th[0]; bfr[2 * jj][1] = th[1];
                bfr[2 * jj + 1][0] = th[2]; bfr[2 * jj + 1][1] = th[3];
            }
#pragma unroll
            for (int i = 0; i < 2; i++)
#pragma unroll
                for (int j = 0; j < 4; j++) {
                    mma16816(acc[i][j], a_hi[i], bfr[j]);
                    mma16816(acc[i][j], a_lo[i], bfr[j]);
                }
        }
    };

    const int NC = KD / BK;
    ldg_stage(0);
    sts_stage(0);
    __syncthreads();
    for (int c = 0; c < NC; c++) {
        if (c + 1 < NC) ldg_stage(c + 1);
        compute_stage(c & 1);
        if (c + 1 < NC) sts_stage((c + 1) & 1);
        __syncthreads();
    }

    // ---- epilogue
    int r_base = wm * 32 + (lane >> 2);
    int c_base = n0 + wn * 32 + 2 * (lane & 3);
#pragma unroll
    for (int i = 0; i < 2; i++) {
#pragma unroll
        for (int h = 0; h < 2; h++) {
            int m = m0 + r_base + i * 16 + h * 8;
            if (m >= cnt) continue;
            size_t orow = (size_t)(base + m);
#pragma unroll
            for (int j = 0; j < 4; j++) {
                int n = c_base + j * 8;
                float v0 = acc[i][j][h * 2];
                float v1 = acc[i][j][h * 2 + 1];
                if (G1) {
                    v0 += __ldg(&bias[(size_t)e * NTOT + n]);
                    v1 += __ldg(&bias[(size_t)e * NTOT + n + 1]);
                    v0 = fmaxf(v0, 0.f); v1 = fmaxf(v1, 0.f);
                    unsigned hh, ll;
                    split2h(v0, v1, hh, ll);
                    *(unsigned*)(g_Hhi + orow * HID + n) = hh;
                    *(unsigned*)(g_Hlo + orow * HID + n) = ll;
                } else {
                    float2 v; v.x = v0; v.y = v1;
                    *(float2*)(g_Hout + orow * DIM + n) = v;
                }
            }
        }
    }
}

// ---------------- combine ----------------------------------------------------
__global__ void combine_kernel(const float* __restrict__ b2,
                               float* __restrict__ out) {
    int t = blockIdx.x;
    int e1 = g_topk_e[t * 2 + 0], e2 = g_topk_e[t * 2 + 1];
    float p1 = g_topk_p[t * 2 + 0], p2 = g_topk_p[t * 2 + 1];
    int r1 = g_tok_row[t * 2 + 0], r2 = g_tok_row[t * 2 + 1];
    const float* h1 = g_Hout + (size_t)r1 * DIM;
    const float* h2 = g_Hout + (size_t)r2 * DIM;
    const float* bb1 = b2 + (size_t)e1 * DIM;
    const float* bb2 = b2 + (size_t)e2 * DIM;
    for (int d = threadIdx.x; d < DIM; d += blockDim.x) {
        out[(size_t)t * DIM + d] = p1 * (h1[d] + bb1[d]) + p2 * (h2[d] + bb2[d]);
    }
}

// ---------------- launch -----------------------------------------------------
extern "C" void kernel_launch(void* const* d_in, const int* in_sizes, int n_in,
                              void* d_out, int out_size) {
    (void)in_sizes; (void)n_in; (void)out_size;
    const float* x  = (const float*)d_in[0];
    const float* gw = (const float*)d_in[1];
    const float* gb = (const float*)d_in[2];
    const float* w1 = (const float*)d_in[3];
    const float* b1 = (const float*)d_in[4];
    const float* w2 = (const float*)d_in[5];
    const float* b2 = (const float*)d_in[6];
    float* out = (float*)d_out;

    cudaFuncSetAttribute((const void*)moe_gemm<DIM, HID, true>,
                         cudaFuncAttributeMaxDynamicSharedMemorySize, GEMM_SMEM);
    cudaFuncSetAttribute((const void*)moe_gemm<HID, DIM, false>,
                         cudaFuncAttributeMaxDynamicSharedMemorySize, GEMM_SMEM);

    init_kernel<<<1, 32>>>();
    gating_kernel<<<T / 8, 256>>>(x, gw, gb);
    scan_kernel<<<1, 32>>>();
    assign_kernel<<<T / 256, 256>>>();

    moe_gemm<DIM, HID, true><<<dim3(HID / BN, E * MT), NTHR, GEMM_SMEM>>>(x, w1, b1);
    moe_gemm<HID, DIM, false><<<dim3(DIM / BN, E * MT), NTHR, GEMM_SMEM>>>(x, w2, b2);

    combine_kernel<<<T, 256>>>(b2, out);
}

// round 11
// speedup vs baseline: 4.5246x; 1.3730x over previous
// R11: byte-equivalent resubmission of the R10 single-plane fp16 kernel.
// R10 failed with "GB300 container failed twice" (infra flake, same signature
// as R5 which passed on identical resubmit). No kernel-side hang surface:
// no mbarrier waits, block-uniform syncthreads, 96 MB statics, 38.9 KB smem.
#include <cuda_runtime.h>
#include <cuda_fp16.h>

#define T    4096
#define DIM  1024
#define HID  4096
#define E    8
#define KTOP 2
#define NROW (T * KTOP)

#define BM 128
#define BN 128
#define BK 32
#define MT 32            // max M-tiles per expert
#define NTHR 512         // 16 warps: 4 (m) x 4 (n), warp tile 32x32

// SMEM layout per stage: A[128][40h], B[32][136h]
#define PL_A     10240           // 128 * 80B
#define PL_B     8704            // 32 * 272B
#define OFF_A    0
#define OFF_B    PL_A
#define STAGE_B  (PL_A + PL_B)           // 18944
#define GEMM_SMEM (1024 + 2 * STAGE_B)   // 38912

// ---------------- static scratch (96 MB total) -------------------------------
__device__ int   g_counts[E];
__device__ int   g_fill[E];
__device__ int   g_offsets[E + 1];
__device__ int   g_topk_e[T * KTOP];
__device__ float g_topk_p[T * KTOP];
__device__ int   g_row_token[NROW];
__device__ int   g_tok_row[T * KTOP];

__device__ __half g_H[(size_t)NROW * HID];     // 64 MB
__device__ float  g_Hout[(size_t)NROW * DIM];  // 32 MB

// ---------------- PTX helpers ------------------------------------------------
__device__ __forceinline__ unsigned smem_u32(const void* p) {
    unsigned a;
    asm("{ .reg .u64 t; cvta.to.shared.u64 t, %1; cvt.u32.u64 %0, t; }" : "=r"(a) : "l"(p));
    return a;
}
__device__ __forceinline__ void ldsm4(unsigned* r, unsigned addr) {
    asm volatile("ldmatrix.sync.aligned.m8n8.x4.shared.b16 {%0,%1,%2,%3}, [%4];"
                 : "=r"(r[0]), "=r"(r[1]), "=r"(r[2]), "=r"(r[3]) : "r"(addr));
}
__device__ __forceinline__ void ldsm4t(unsigned* r, unsigned addr) {
    asm volatile("ldmatrix.sync.aligned.m8n8.x4.trans.shared.b16 {%0,%1,%2,%3}, [%4];"
                 : "=r"(r[0]), "=r"(r[1]), "=r"(r[2]), "=r"(r[3]) : "r"(addr));
}
__device__ __forceinline__ void mma16816(float* c, const unsigned* a, const unsigned* b) {
    asm volatile(
        "mma.sync.aligned.m16n8k16.row.col.f32.f16.f16.f32 "
        "{%0,%1,%2,%3}, {%4,%5,%6,%7}, {%8,%9}, {%0,%1,%2,%3};"
        : "+f"(c[0]), "+f"(c[1]), "+f"(c[2]), "+f"(c[3])
        : "r"(a[0]), "r"(a[1]), "r"(a[2]), "r"(a[3]), "r"(b[0]), "r"(b[1]));
}
// round two fp32 into packed fp16x2
__device__ __forceinline__ unsigned pack2h(float a, float b) {
    __half2 H = __halves2half2(__float2half_rn(a), __float2half_rn(b));
    return *(unsigned*)&H;
}

// ---------------- init -------------------------------------------------------
__global__ void init_kernel() {
    int i = threadIdx.x;
    if (i < E) { g_counts[i] = 0; g_fill[i] = 0; }
}

// ---------------- gating (exact fp32; one warp per token) --------------------
__global__ void gating_kernel(const float* __restrict__ x,
                              const float* __restrict__ gw,
                              const float* __restrict__ gb) {
    int warp = (blockIdx.x * blockDim.x + threadIdx.x) >> 5;
    int lane = threadIdx.x & 31;
    if (warp >= T) return;
    const float* xr = x + (size_t)warp * DIM;

    float acc[E];
#pragma unroll
    for (int e = 0; e < E; e++) acc[e] = 0.f;
    for (int d = lane; d < DIM; d += 32) {
        float xv = xr[d];
        float4 g0 = *(const float4*)(gw + d * E);
        float4 g1 = *(const float4*)(gw + d * E + 4);
        acc[0] += xv * g0.x; acc[1] += xv * g0.y;
        acc[2] += xv * g0.z; acc[3] += xv * g0.w;
        acc[4] += xv * g1.x; acc[5] += xv * g1.y;
        acc[6] += xv * g1.z; acc[7] += xv * g1.w;
    }
#pragma unroll
    for (int e = 0; e < E; e++)
#pragma unroll
        for (int off = 16; off > 0; off >>= 1)
            acc[e] += __shfl_down_sync(0xffffffffu, acc[e], off);

    if (lane == 0) {
        float lg[E];
        float m = -1e30f;
#pragma unroll
        for (int e = 0; e < E; e++) { lg[e] = acc[e] + gb[e]; m = fmaxf(m, lg[e]); }
        float s = 0.f;
#pragma unroll
        for (int e = 0; e < E; e++) { lg[e] = expf(lg[e] - m); s += lg[e]; }
        int e1 = 0;
#pragma unroll
        for (int e = 1; e < E; e++) if (lg[e] > lg[e1]) e1 = e;
        int e2 = (e1 == 0) ? 1 : 0;
#pragma unroll
        for (int e = 0; e < E; e++) if (e != e1 && e != e2 && lg[e] > lg[e2]) e2 = e;
        float inv = 1.0f / s;
        g_topk_e[warp * 2 + 0] = e1;
        g_topk_e[warp * 2 + 1] = e2;
        g_topk_p[warp * 2 + 0] = lg[e1] * inv;
        g_topk_p[warp * 2 + 1] = lg[e2] * inv;
        atomicAdd(&g_counts[e1], 1);
        atomicAdd(&g_counts[e2], 1);
    }
}

__global__ void scan_kernel() {
    if (threadIdx.x == 0) {
        int acc = 0;
        g_offsets[0] = 0;
        for (int e = 0; e < E; e++) { acc += g_counts[e]; g_offsets[e + 1] = acc; }
    }
}

__global__ void assign_kernel() {
    int t = blockIdx.x * blockDim.x + threadIdx.x;
    if (t >= T) return;
#pragma unroll
    for (int k = 0; k < KTOP; k++) {
        int e = g_topk_e[t * 2 + k];
        int slot = atomicAdd(&g_fill[e], 1);
        int row = g_offsets[e] + slot;
        g_row_token[row] = t;
        g_tok_row[t * 2 + k] = row;
    }
}

// ---------------- grouped HMMA GEMM (fp16 x fp16, fp32 acc) ------------------
// G1: C[rows,HID] = gather(x)@w1, +b1, ReLU -> g_H (fp16)
// G2: C[rows,DIM] = H @ w2 -> g_Hout (fp32)
// fp32 sources rounded to fp16 during the STS phase.
// 16 warps: 4 (m) x 4 (n); warp tile 32x32; 1 MMA per frag pair.
template <int KD, int NTOT, bool G1>
__global__ void __launch_bounds__(NTHR, 1)
moe_gemm(const float* __restrict__ xA,
         const float* __restrict__ wB,    // [E][KD][NTOT] fp32 (k-major rows)
         const float* __restrict__ bias) {
    int e  = blockIdx.y >> 5;
    int mt = blockIdx.y & 31;
    int cnt = g_counts[e];
    int m0 = mt * BM;
    if (m0 >= cnt) return;
    int n0 = blockIdx.x * BN;
    int base = g_offsets[e];

    extern __shared__ char smem[];
    int* toks = (int*)smem;
    char* tiles = smem + 1024;

    int tid  = threadIdx.x;
    int lane = tid & 31;
    int wid  = tid >> 5;

    if (G1 && tid < BM) {
        int m = m0 + tid;
        toks[tid] = g_row_token[base + (m < cnt ? m : cnt - 1)];
    }
    __syncthreads();

    // ---- load mapping: A: 4 threads/row (8 k each); B: 16 threads/k-row (8 n each)
    int arow = tid >> 2, kh = (tid & 3) * 8;
    int brow = tid >> 4, nh = (tid & 15) * 8;

    const float* aF = nullptr;
    const __half* aH = nullptr;
    if (G1) {
        aF = xA + (size_t)toks[arow] * KD + kh;
    } else {
        int m = m0 + arow; if (m >= cnt) m = cnt - 1;
        aH = g_H + (size_t)(base + m) * KD + kh;
    }
    const float* bF = wB + ((size_t)e * KD + brow) * NTOT + n0 + nh;

    unsigned aoff = (unsigned)(arow * 80 + kh * 2);
    unsigned boff = (unsigned)(brow * 272 + nh * 2);

    // ---- staged registers
    float fa[8];
    uint4 ha;
    float fb[8];

    auto ldg_stage = [&](int c) {
        int kk = c * BK;
        if (G1) {
            *(float4*)(fa)     = __ldg((const float4*)(aF + kk));
            *(float4*)(fa + 4) = __ldg((const float4*)(aF + kk + 4));
        } else {
            ha = __ldg((const uint4*)(aH + kk));
        }
        const float* bp = bF + (size_t)kk * NTOT;
        *(float4*)(fb)     = __ldg((const float4*)(bp));
        *(float4*)(fb + 4) = __ldg((const float4*)(bp + 4));
    };

    auto sts_stage = [&](int st) {
        char* stb = tiles + st * STAGE_B;
        if (G1) {
            unsigned h[4];
#pragma unroll
            for (int q = 0; q < 4; q++) h[q] = pack2h(fa[2 * q], fa[2 * q + 1]);
            *(uint4*)(stb + OFF_A + aoff) = make_uint4(h[0], h[1], h[2], h[3]);
        } else {
            *(uint4*)(stb + OFF_A + aoff) = ha;
        }
        unsigned h[4];
#pragma unroll
        for (int q = 0; q < 4; q++) h[q] = pack2h(fb[2 * q], fb[2 * q + 1]);
        *(uint4*)(stb + OFF_B + boff) = make_uint4(h[0], h[1], h[2], h[3]);
    };

    // ---- compute mapping: warp (wm, wn) owns 32x32
    int wm = wid >> 2;     // 0..3
    int wn = wid & 3;      // 0..3
    unsigned sbase = smem_u32(tiles);
    unsigned a_off = (unsigned)(((wm * 32 + (lane & 15)) * 40 + (lane >> 4) * 8) * 2);
    unsigned b_off = (unsigned)((lane & 15) * 272 + (wn * 32 + (lane >> 4) * 8) * 2);

    float acc[2][4][4];
#pragma unroll
    for (int i = 0; i < 2; i++)
#pragma unroll
        for (int j = 0; j < 4; j++)
#pragma unroll
            for (int q = 0; q < 4; q++) acc[i][j][q] = 0.f;

    auto compute_stage = [&](int st) {
        unsigned stb = sbase + st * STAGE_B;
#pragma unroll
        for (int ks = 0; ks < 2; ks++) {
            unsigned afr[2][4], bfr[4][2];
#pragma unroll
            for (int i = 0; i < 2; i++) {
                unsigned ad = stb + a_off + (unsigned)(i * 16 * 80) + (unsigned)(ks * 32);
                ldsm4(afr[i], ad + OFF_A);
            }
#pragma unroll
            for (int jj = 0; jj < 2; jj++) {
                unsigned bd = stb + b_off + (unsigned)(ks * 16 * 272) + (unsigned)(jj * 32);
                unsigned th[4];
                ldsm4t(th, bd + OFF_B);
                bfr[2 * jj][0] = th[0]; bfr[2 * jj][1] = th[1];
                bfr[2 * jj + 1][0] = th[2]; bfr[2 * jj + 1][1] = th[3];
            }
#pragma unroll
            for (int i = 0; i < 2; i++)
#pragma unroll
                for (int j = 0; j < 4; j++)
                    mma16816(acc[i][j], afr[i], bfr[j]);
        }
    };

    const int NC = KD / BK;
    ldg_stage(0);
    sts_stage(0);
    __syncthreads();
    for (int c = 0; c < NC; c++) {
        if (c + 1 < NC) ldg_stage(c + 1);
        compute_stage(c & 1);
        if (c + 1 < NC) sts_stage((c + 1) & 1);
        __syncthreads();
    }

    // ---- epilogue
    int r_base = wm * 32 + (lane >> 2);
    int c_base = n0 + wn * 32 + 2 * (lane & 3);
#pragma unroll
    for (int i = 0; i < 2; i++) {
#pragma unroll
        for (int h = 0; h < 2; h++) {
            int m = m0 + r_base + i * 16 + h * 8;
            if (m >= cnt) continue;
            size_t orow = (size_t)(base + m);
#pragma unroll
            for (int j = 0; j < 4; j++) {
                int n = c_base + j * 8;
                float v0 = acc[i][j][h * 2];
                float v1 = acc[i][j][h * 2 + 1];
                if (G1) {
                    v0 += __ldg(&bias[(size_t)e * NTOT + n]);
                    v1 += __ldg(&bias[(size_t)e * NTOT + n + 1]);
                    v0 = fmaxf(v0, 0.f); v1 = fmaxf(v1, 0.f);
                    *(unsigned*)(g_H + orow * HID + n) = pack2h(v0, v1);
                } else {
                    float2 v; v.x = v0; v.y = v1;
                    *(float2*)(g_Hout + orow * DIM + n) = v;
                }
            }
        }
    }
}

// ---------------- combine ----------------------------------------------------
__global__ void combine_kernel(const float* __restrict__ b2,
                               float* __restrict__ out) {
    int t = blockIdx.x;
    int e1 = g_topk_e[t * 2 + 0], e2 = g_topk_e[t * 2 + 1];
    float p1 = g_topk_p[t * 2 + 0], p2 = g_topk_p[t * 2 + 1];
    int r1 = g_tok_row[t * 2 + 0], r2 = g_tok_row[t * 2 + 1];
    const float* h1 = g_Hout + (size_t)r1 * DIM;
    const float* h2 = g_Hout + (size_t)r2 * DIM;
    const float* bb1 = b2 + (size_t)e1 * DIM;
    const float* bb2 = b2 + (size_t)e2 * DIM;
    for (int d = threadIdx.x; d < DIM; d += blockDim.x) {
        out[(size_t)t * DIM + d] = p1 * (h1[d] + bb1[d]) + p2 * (h2[d] + bb2[d]);
    }
}

// ---------------- launch -----------------------------------------------------
extern "C" void kernel_launch(void* const* d_in, const int* in_sizes, int n_in,
                              void* d_out, int out_size) {
    (void)in_sizes; (void)n_in; (void)out_size;
    const float* x  = (const float*)d_in[0];
    const float* gw = (const float*)d_in[1];
    const float* gb = (const float*)d_in[2];
    const float* w1 = (const float*)d_in[3];
    const float* b1 = (const float*)d_in[4];
    const float* w2 = (const float*)d_in[5];
    const float* b2 = (const float*)d_in[6];
    float* out = (float*)d_out;

    cudaFuncSetAttribute((const void*)moe_gemm<DIM, HID, true>,
                         cudaFuncAttributeMaxDynamicSharedMemorySize, GEMM_SMEM);
    cudaFuncSetAttribute((const void*)moe_gemm<HID, DIM, false>,
                         cudaFuncAttributeMaxDynamicSharedMemorySize, GEMM_SMEM);

    init_kernel<<<1, 32>>>();
    gating_kernel<<<T / 8, 256>>>(x, gw, gb);
    scan_kernel<<<1, 32>>>();
    assign_kernel<<<T / 256, 256>>>();

    moe_gemm<DIM, HID, true><<<dim3(HID / BN, E * MT), NTHR, GEMM_SMEM>>>(x, w1, b1);
    moe_gemm<HID, DIM, false><<<dim3(DIM / BN, E * MT), NTHR, GEMM_SMEM>>>(x, w2, b2);

    combine_kernel<<<T, 256>>>(b2, out);
}